// round 5
// baseline (speedup 1.0000x reference)
#include <cuda_runtime.h>
#include <cuda_bf16.h>
#include <cstdint>

#define N_MAX   100000
#define E_MAX   1600000
#define HID     64
#define IN_DIM  128

// ---------------- scratch (device globals; no allocation allowed) ----------
__device__ float g_h[N_MAX * HID];       // MLP output features
__device__ float g_rnorm[N_MAX];         // 1 / max(||h||, 1e-12)
__device__ int   g_src[E_MAX];
__device__ int   g_dst[E_MAX];
__device__ int   g_rank[E_MAX];
__device__ int   g_deg[N_MAX];
__device__ int   g_incl[N_MAX];
__device__ int   g_rs[N_MAX];
__device__ int   g_re[N_MAX];
__device__ int   g_csr[E_MAX];
__device__ int   g_bsum[1024];
__device__ int   g_boff[1024];
__device__ int   g_is64;

typedef unsigned long long ull;

// ---------------- f32x2 packed helpers (Blackwell sm_100 PTX) --------------
__device__ __forceinline__ void ffma2(ull& d, ull a, ull b) {
    asm("fma.rn.f32x2 %0, %1, %2, %0;" : "+l"(d) : "l"(a), "l"(b));
}
__device__ __forceinline__ ull pack2(float x, float y) {
    ull r; asm("mov.b64 %0, {%1, %2};" : "=l"(r) : "f"(x), "f"(y)); return r;
}
__device__ __forceinline__ void unpack2(ull v, float& x, float& y) {
    asm("mov.b64 {%0, %1}, %2;" : "=f"(x), "=f"(y) : "l"(v));
}

// ---------------- init: zero degrees + detect edge dtype -------------------
__global__ void k_init(const void* ei, int E, int N) {
    int i = blockIdx.x * blockDim.x + threadIdx.x;
    if (i < N) g_deg[i] = 0;
    if (blockIdx.x == 0 && threadIdx.x < 32) {
        const long long* p = (const long long*)ei;
        int lane = threadIdx.x;
        bool bad = false;
        for (int k = lane; k < 64 && k < E; k += 32) {
            long long v = p[k];
            if (v < 0 || v >= (long long)N) bad = true;
        }
        unsigned m = __ballot_sync(0xffffffffu, bad);
        if (lane == 0) g_is64 = (m == 0);
    }
}

// convert to int32 + count in-degrees, remember rank within dst segment
__global__ void k_convcount(const void* ei, int E) {
    int e = blockIdx.x * blockDim.x + threadIdx.x;
    if (e >= E) return;
    int s, d;
    if (g_is64) {
        const long long* p = (const long long*)ei;
        s = (int)p[e];
        d = (int)p[(long long)E + e];
    } else {
        const int* p = (const int*)ei;
        s = p[e];
        d = p[E + e];
    }
    g_src[e] = s;
    g_dst[e] = d;
    g_rank[e] = atomicAdd(&g_deg[d], 1);
}

// ---------------- shfl-based prefix scans ----------------------------------
__global__ void k_scan1(int N) {
    __shared__ int wsum[32];
    int t = threadIdx.x;
    int i = blockIdx.x * 1024 + t;
    int lane = t & 31, wid = t >> 5;
    int v = (i < N) ? g_deg[i] : 0;
    int sc = v;
#pragma unroll
    for (int o = 1; o < 32; o <<= 1) {
        int u = __shfl_up_sync(0xffffffffu, sc, o);
        if (lane >= o) sc += u;
    }
    if (lane == 31) wsum[wid] = sc;
    __syncthreads();
    if (wid == 0) {
        int wv = wsum[lane];
        int ws = wv;
#pragma unroll
        for (int o = 1; o < 32; o <<= 1) {
            int u = __shfl_up_sync(0xffffffffu, ws, o);
            if (lane >= o) ws += u;
        }
        wsum[lane] = ws - wv;   // exclusive warp offsets
        if (lane == 31) g_bsum[blockIdx.x] = ws;
    }
    __syncthreads();
    if (i < N) g_incl[i] = sc + wsum[wid];
}

__global__ void k_scan2(int nblk) {
    __shared__ int wsum[32];
    int t = threadIdx.x;
    int lane = t & 31, wid = t >> 5;
    int v = (t < nblk) ? g_bsum[t] : 0;
    int sc = v;
#pragma unroll
    for (int o = 1; o < 32; o <<= 1) {
        int u = __shfl_up_sync(0xffffffffu, sc, o);
        if (lane >= o) sc += u;
    }
    if (lane == 31) wsum[wid] = sc;
    __syncthreads();
    if (wid == 0) {
        int wv = wsum[lane];
        int ws = wv;
#pragma unroll
        for (int o = 1; o < 32; o <<= 1) {
            int u = __shfl_up_sync(0xffffffffu, ws, o);
            if (lane >= o) ws += u;
        }
        wsum[lane] = ws - wv;
    }
    __syncthreads();
    g_boff[t] = sc + wsum[wid] - v;   // exclusive
}

__global__ void k_scan3(int N) {
    int i = blockIdx.x * blockDim.x + threadIdx.x;
    if (i >= N) return;
    int tot = g_incl[i] + g_boff[i >> 10];
    g_rs[i] = tot - g_deg[i];
    g_re[i] = tot;
}

__global__ void k_scatter(int E) {
    int e = blockIdx.x * blockDim.x + threadIdx.x;
    if (e >= E) return;
    int pos = g_rs[g_dst[e]] + g_rank[e];
    g_csr[pos] = g_src[e];
}

// ---------------- MLP: f32x2 packed SIMT, 64 nodes/CTA, 256 threads --------
// smem: W1s[128][64] | W2s[64][64] | bias[128] | region{xs_t -> ht_t+stage}
#define W1S_OFF   0            // 32768 B
#define W2S_OFF   32768        // 16384 B
#define BIAS_OFF  49152        // 512 B
#define XT_OFF    49664        // xs_t: 128 x 66 floats = 33792 B
#define HT_OFF    49664        // ht_t: 64 x 66 floats = 16896 B (reuse)
#define STG_OFF   66560        // stage: 64 x 66 floats = 16896 B
#define SMEM_SZ   83456

__global__ void __launch_bounds__(256, 2) k_mlp(
    const float* __restrict__ x, const float* __restrict__ b1,
    const float* __restrict__ b2, const float* __restrict__ W1,
    const float* __restrict__ W2, int N)
{
    extern __shared__ char sm[];
    float* W1s = (float*)(sm + W1S_OFF);
    float* W2s = (float*)(sm + W2S_OFF);
    float* bias = (float*)(sm + BIAS_OFF);
    float* xs_t = (float*)(sm + XT_OFF);
    float* ht_t = (float*)(sm + HT_OFF);
    float* stage = (float*)(sm + STG_OFF);

    int tid = threadIdx.x;
    int wid = tid >> 5, lane = tid & 31;
    int node0 = blockIdx.x * 64;
    int w8 = wid * 8;

    // loads: W1 (2048 f4), W2 (1024 f4), bias
    {
        const float4* s1 = (const float4*)W1;
        float4* d1 = (float4*)W1s;
        for (int i = tid; i < 2048; i += 256) d1[i] = s1[i];
        const float4* s2 = (const float4*)W2;
        float4* d2 = (float4*)W2s;
        for (int i = tid; i < 1024; i += 256) d2[i] = s2[i];
        if (tid < 64) { bias[tid] = b1[tid]; bias[64 + tid] = b2[tid]; }
    }
    // x transpose into xs_t[i*66 + n]
    {
        for (int idx = tid; idx < 64 * 128; idx += 256) {
            int n = idx >> 7, i = idx & 127;
            int node = node0 + n;
            float v = (node < N) ? x[(size_t)node * 128 + i] : 0.f;
            xs_t[i * 66 + n] = v;
        }
    }
    __syncthreads();

    // ---- GEMM1: acc[half][np] = packed (h[n0][c], h[n1][c]) ----
    ull acc0[4], acc1[4];
#pragma unroll
    for (int p = 0; p < 4; p++) { acc0[p] = 0ull; acc1[p] = 0ull; }

#pragma unroll 2
    for (int i = 0; i < 128; i++) {
        float w0 = W1s[i * 64 + lane];
        float w1 = W1s[i * 64 + lane + 32];
        ull wp0 = pack2(w0, w0);
        ull wp1 = pack2(w1, w1);
        const ull* xr = (const ull*)(xs_t + i * 66 + w8);
#pragma unroll
        for (int p = 0; p < 4; p++) {
            ull a = xr[p];
            ffma2(acc0[p], a, wp0);
            ffma2(acc1[p], a, wp1);
        }
    }
    __syncthreads();   // all GEMM1 xs_t reads done before ht_t overwrite

    // epilogue1: relu(+b1) -> ht_t[c*66 + n]
    {
        float bA = bias[lane], bB = bias[lane + 32];
#pragma unroll
        for (int p = 0; p < 4; p++) {
            float hx, hy;
            unpack2(acc0[p], hx, hy);
            ht_t[lane * 66 + w8 + 2 * p]     = fmaxf(hx + bA, 0.f);
            ht_t[lane * 66 + w8 + 2 * p + 1] = fmaxf(hy + bA, 0.f);
            unpack2(acc1[p], hx, hy);
            ht_t[(lane + 32) * 66 + w8 + 2 * p]     = fmaxf(hx + bB, 0.f);
            ht_t[(lane + 32) * 66 + w8 + 2 * p + 1] = fmaxf(hy + bB, 0.f);
        }
    }
    __syncthreads();

    // ---- GEMM2 ----
#pragma unroll
    for (int p = 0; p < 4; p++) { acc0[p] = 0ull; acc1[p] = 0ull; }
#pragma unroll 2
    for (int i = 0; i < 64; i++) {
        float w0 = W2s[i * 64 + lane];
        float w1 = W2s[i * 64 + lane + 32];
        ull wp0 = pack2(w0, w0);
        ull wp1 = pack2(w1, w1);
        const ull* hr = (const ull*)(ht_t + i * 66 + w8);
#pragma unroll
        for (int p = 0; p < 4; p++) {
            ull a = hr[p];
            ffma2(acc0[p], a, wp0);
            ffma2(acc1[p], a, wp1);
        }
    }

    // epilogue2: +b2 -> stage[n*66 + c]
    {
        float bA = bias[64 + lane], bB = bias[64 + lane + 32];
#pragma unroll
        for (int p = 0; p < 4; p++) {
            float hx, hy;
            unpack2(acc0[p], hx, hy);
            stage[(w8 + 2 * p) * 66 + lane]     = hx + bA;
            stage[(w8 + 2 * p + 1) * 66 + lane] = hy + bA;
            unpack2(acc1[p], hx, hy);
            stage[(w8 + 2 * p) * 66 + lane + 32]     = hx + bB;
            stage[(w8 + 2 * p + 1) * 66 + lane + 32] = hy + bB;
        }
    }
    __syncthreads();

    // norms + coalesced global store (warp w handles its 8 nodes)
    {
        float2* gh2 = (float2*)g_h;
        const float2* st2 = (const float2*)stage;
#pragma unroll
        for (int r = 0; r < 8; r++) {
            int n = w8 + r;
            int node = node0 + n;
            float2 v = st2[n * 33 + lane];
            float ss = v.x * v.x + v.y * v.y;
#pragma unroll
            for (int o = 16; o; o >>= 1) ss += __shfl_xor_sync(0xffffffffu, ss, o);
            if (node < N) {
                gh2[(size_t)node * 32 + lane] = v;
                if (lane == 0) g_rnorm[node] = 1.f / fmaxf(sqrtf(ss), 1e-12f);
            }
        }
    }
}

// ---------------- gather: fixed-shift segment-softmax + agg + classifier ---
__global__ void __launch_bounds__(256) k_gather(
    const float* __restrict__ beta_p, const float* __restrict__ Wc,
    const float* __restrict__ bc, float* __restrict__ out, int N)
{
    int wid = threadIdx.x >> 5;
    int lane = threadIdx.x & 31;
    int n = blockIdx.x * 8 + wid;
    if (n >= N) return;

    float beta = __ldg(beta_p);
    float C = fabsf(beta);     // |e| <= |beta| always -> fixed softmax shift
    const float2* h2 = (const float2*)g_h;
    float2 hd = h2[(size_t)n * 32 + lane];
    float rnd = g_rnorm[n];

    float p = hd.x * hd.x + hd.y * hd.y;
#pragma unroll
    for (int o = 16; o; o >>= 1) p += __shfl_xor_sync(0xffffffffu, p, o);
    float e_self = beta * p * rnd * rnd;
    float w = __expf(e_self - C);
    float s = w;
    float2 acc = make_float2(w * hd.x, w * hd.y);

    int start = g_rs[n], end = g_re[n];
    float brnd = beta * rnd;
    for (int base = start; base < end; base += 32) {
        int k = base + lane;
        int sidx = (k < end) ? g_csr[k] : 0;
        float cj = (k < end) ? brnd * g_rnorm[sidx] : 0.f;
        int cnt = min(32, end - base);
        for (int j0 = 0; j0 < cnt; j0 += 8) {
            float2 hsv[8];
            float cv[8];
#pragma unroll
            for (int jj = 0; jj < 8; jj++) {
                int j = j0 + jj;
                int sj = __shfl_sync(0xffffffffu, sidx, j & 31);
                cv[jj] = __shfl_sync(0xffffffffu, cj, j & 31);
                hsv[jj] = make_float2(0.f, 0.f);
                if (j < cnt) hsv[jj] = h2[(size_t)sj * 32 + lane];
            }
#pragma unroll
            for (int jj = 0; jj < 8; jj++) {
                int j = j0 + jj;
                float d = hd.x * hsv[jj].x + hd.y * hsv[jj].y;
#pragma unroll
                for (int o = 16; o; o >>= 1) d += __shfl_xor_sync(0xffffffffu, d, o);
                if (j < cnt) {
                    float wj = __expf(cv[jj] * d - C);
                    s += wj;
                    acc.x += wj * hsv[jj].x;
                    acc.y += wj * hsv[jj].y;
                }
            }
        }
    }

    float inv = 1.f / (s + 1e-16f);
    float ox = acc.x * inv, oy = acc.y * inv;

    float2 wc0 = ((const float2*)Wc)[lane * 2];
    float2 wc1 = ((const float2*)Wc)[lane * 2 + 1];
    float y0 = ox * wc0.x + oy * wc1.x;
    float y1 = ox * wc0.y + oy * wc1.y;
#pragma unroll
    for (int o = 16; o; o >>= 1) {
        y0 += __shfl_xor_sync(0xffffffffu, y0, o);
        y1 += __shfl_xor_sync(0xffffffffu, y1, o);
    }
    if (lane == 0) {
        out[(size_t)n * 2]     = y0 + bc[0];
        out[(size_t)n * 2 + 1] = y1 + bc[1];
    }
}

// ---------------- launch ---------------------------------------------------
extern "C" void kernel_launch(void* const* d_in, const int* in_sizes, int n_in,
                              void* d_out, int out_size)
{
    const float* x    = (const float*)d_in[0];
    const void*  ei   = d_in[1];
    const float* W1   = (const float*)d_in[2];
    const float* b1   = (const float*)d_in[3];
    const float* W2   = (const float*)d_in[4];
    const float* b2   = (const float*)d_in[5];
    const float* beta = (const float*)d_in[6];
    const float* Wc   = (const float*)d_in[7];
    const float* bc   = (const float*)d_in[8];
    float* y = (float*)d_out;

    int hid    = in_sizes[3];            // 64
    int in_dim = in_sizes[2] / hid;      // 128
    int N      = in_sizes[0] / in_dim;   // 100000
    int E      = in_sizes[1] / 2;        // 1600000

    cudaFuncSetAttribute(k_mlp, cudaFuncAttributeMaxDynamicSharedMemorySize, SMEM_SZ);

    int nblk = (N + 1023) / 1024;

    k_init<<<(N + 255) / 256, 256>>>(ei, E, N);          // 1
    k_convcount<<<(E + 255) / 256, 256>>>(ei, E);        // 2
    k_scan1<<<nblk, 1024>>>(N);                          // 3
    k_mlp<<<(N + 63) / 64, 256, SMEM_SZ>>>(x, b1, b2, W1, W2, N);  // 4 <- profiled
    k_scan2<<<1, 1024>>>(nblk);                          // 5
    k_scan3<<<(N + 255) / 256, 256>>>(N);                // 6
    k_scatter<<<(E + 255) / 256, 256>>>(E);              // 7
    k_gather<<<(N + 7) / 8, 256>>>(beta, Wc, bc, y, N);  // 8
}